// round 15
// baseline (speedup 1.0000x reference)
#include <cuda_runtime.h>

// Problem constants (fixed shapes from setup_inputs)
#define NB      64
#define T_LEN   2048
#define DDIM    80
#define N_ROWS  (NB * T_LEN)          // 131072
#define N_ELEM  (N_ROWS * DDIM)       // 10,485,760
#define VPR     (DDIM / 4)            // 20 float4 per row

#define GTHREADS 256
#define GBLOCKS  1180                 // stride % 20 == 0
#define STRIDE   (GBLOCKS * GTHREADS) // 302080 = 20 * 15104
#define ROWSTEP  (STRIDE / VPR)       // 15104 rows per loop step

// Scratch (no device allocation allowed)
__device__ float        g_pc[GBLOCKS];
__device__ float        g_pl[GBLOCKS];
__device__ unsigned int g_count = 0;
__device__ __align__(16) float g_zero[DDIM];   // zero-initialized row

__device__ __forceinline__ float lg2f(float x) {
    float y; asm("lg2.approx.f32 %0, %1;" : "=f"(y) : "f"(x)); return y;
}

// exp(-32*|d|) approx, no conversion instruction (R12/R13-proven, 7.7e-5):
// target bits i = B - A*|d|; encode i/256 in the float window [2^23, 2^24):
//   f = fma(min(|d|,2.74), -A/256, 2^23 + B/256); bits(f) << 8 == i exactly
// because the window anchor 0x4B000000 << 8 == 0 (mod 2^32).
// Clamped tail (d>2.74) yields a ~5e-39 denormal vs true <=8.6e-39 — absorbed
// by the 1e-37 seed on the softmin sum.
__device__ __forceinline__ float fexp2n(float d) {    // d = signed raw diff
    float dc = fminf(fabsf(d), 2.74f);                // FMNMX, |.| folded
    float f  = fmaf(dc, -1512775.3957f, 12548296.2f); // FFMA-imm, RN rounds
    return __uint_as_float(__float_as_uint(f) << 8);  // SHF only
}

__global__ void __launch_bounds__(GTHREADS)
jitter_fused(const float* __restrict__ in, const float* __restrict__ tg,
             float* __restrict__ out)
{
    const unsigned t = blockIdx.x * GTHREADS + threadIdx.x;

    // Loop-invariant (STRIDE is a multiple of VPR): computed exactly once.
    const unsigned jj = t % VPR;          // float4 slot within row
    const unsigned r0 = t / VPR;          // starting row
    const int  base = jj * 4;
    const bool lv   = (jj > 0);
    const bool rv   = (jj < VPR - 1);

    // Dual accumulators: break the serial FADD chains behind lg2 (lat 16).
    float accC0 = 0.0f, accC1 = 0.0f;
    float accL0 = 0.0f, accL1 = 0.0f;

    #pragma unroll 2
    for (unsigned row = r0; row < N_ROWS; row += ROWSTEP) {
        const unsigned i = row & (T_LEN - 1);

        const float* ip = in + (size_t)row * DDIM + base;
        const float* tp = tg + (size_t)row * DDIM + base;

        // Branch-free row edges: off-edge row reads a zero row instead of
        // taking a BSSY/BSYNC-guarded zero-fill arm.
        const float* pu = (i > 0)         ? tp - DDIM : g_zero + base;
        const float* pd = (i < T_LEN - 1) ? tp + DDIM : g_zero + base;

        float4 x4 = *reinterpret_cast<const float4*>(ip);

        float4 u4 = *reinterpret_cast<const float4*>(pu);
        float4 m4 = *reinterpret_cast<const float4*>(tp);
        float4 b4 = *reinterpret_cast<const float4*>(pd);

        float uL = lv ? pu[-1] : 0.0f;
        float mL = lv ? tp[-1] : 0.0f;
        float bL = lv ? pd[-1] : 0.0f;
        float uR = rv ? pu[4]  : 0.0f;
        float mR = rv ? tp[4]  : 0.0f;
        float bR = rv ? pd[4]  : 0.0f;

        float tu[6] = {uL, u4.x, u4.y, u4.z, u4.w, uR};
        float tm[6] = {mL, m4.x, m4.y, m4.z, m4.w, mR};
        float tb[6] = {bL, b4.x, b4.y, b4.z, b4.w, bR};
        float x[4]  = {x4.x, x4.y, x4.z, x4.w};

        #pragma unroll
        for (int e = 0; e < 4; e++) {
            float xv = x[e];
            float dcen = xv - tm[e + 1];              // center diff (signed)
            float s0 = 1e-37f + fexp2n(dcen);         // underflow-guard seed
            float s1 = fexp2n(xv - tu[e + 0]);
            float s2 = fexp2n(xv - tu[e + 1]);
            float s3 = fexp2n(xv - tu[e + 2]);
            s0 += fexp2n(xv - tm[e + 0]);
            s1 += fexp2n(xv - tm[e + 2]);
            s2 += fexp2n(xv - tb[e + 0]);
            s3 += fexp2n(xv - tb[e + 1]);
            s0 += fexp2n(xv - tb[e + 2]);
            float s = (s0 + s1) + (s2 + s3);
            if (e & 1) { accC1 += fabsf(dcen); accL1 += lg2f(s); }
            else       { accC0 += fabsf(dcen); accL0 += lg2f(s); }
        }
    }

    float accC = accC0 + accC1;
    float accL = accL0 + accL1;

    // ---- deterministic block tree reduction ----
    __shared__ float shc[GTHREADS];
    __shared__ float shl[GTHREADS];
    shc[threadIdx.x] = accC;
    shl[threadIdx.x] = accL;
    __syncthreads();
    #pragma unroll
    for (int off = GTHREADS / 2; off > 0; off >>= 1) {
        if (threadIdx.x < off) {
            shc[threadIdx.x] += shc[threadIdx.x + off];
            shl[threadIdx.x] += shl[threadIdx.x + off];
        }
        __syncthreads();
    }

    // ---- fused final reduction via ticket (last block) ----
    __shared__ bool isLast;
    if (threadIdx.x == 0) {
        g_pc[blockIdx.x] = shc[0];
        g_pl[blockIdx.x] = shl[0];
        __threadfence();
        unsigned ticket = atomicAdd(&g_count, 1u);
        isLast = (ticket == GBLOCKS - 1);
    }
    __syncthreads();

    if (isLast) {
        __shared__ double dsc[GTHREADS];
        __shared__ double dsl[GTHREADS];
        double dc = 0.0, dl = 0.0;
        for (int k = threadIdx.x; k < GBLOCKS; k += GTHREADS) {
            dc += (double)__ldcg(&g_pc[k]);
            dl += (double)__ldcg(&g_pl[k]);
        }
        dsc[threadIdx.x] = dc;
        dsl[threadIdx.x] = dl;
        __syncthreads();
        #pragma unroll
        for (int off = GTHREADS / 2; off > 0; off >>= 1) {
            if (threadIdx.x < off) {
                dsc[threadIdx.x] += dsc[threadIdx.x + off];
                dsl[threadIdx.x] += dsl[threadIdx.x + off];
            }
            __syncthreads();
        }
        if (threadIdx.x == 0) {
            const double C2d = -0.021660849392498291;  // -ln(2)/32
            double res = (0.5 / (double)N_ELEM) * (dsc[0] + C2d * dsl[0]);
            out[0] = (float)res;
            g_count = 0;   // reset ticket for graph replay
        }
    }
}

extern "C" void kernel_launch(void* const* d_in, const int* in_sizes, int n_in,
                              void* d_out, int out_size)
{
    const float* in = (const float*)d_in[0];
    const float* tg = (const float*)d_in[1];
    float* out = (float*)d_out;

    jitter_fused<<<GBLOCKS, GTHREADS>>>(in, tg, out);
}

// round 17
// speedup vs baseline: 1.0529x; 1.0529x over previous
#include <cuda_runtime.h>
#include <cuda_bf16.h>

// Problem constants (fixed shapes from setup_inputs)
#define NB      64
#define T_LEN   2048
#define DDIM    80
#define N_ROWS  (NB * T_LEN)          // 131072
#define N_ELEM  (N_ROWS * DDIM)       // 10,485,760
#define VPR     (DDIM / 4)            // 20 float4 per row

#define GTHREADS 256
#define GBLOCKS  1180                 // stride % 20 == 0
#define STRIDE   (GBLOCKS * GTHREADS) // 302080 = 20 * 15104
#define ROWSTEP  (STRIDE / VPR)       // 15104 rows per loop step

// Scratch (no device allocation allowed)
__device__ float        g_pc[GBLOCKS];
__device__ float        g_pl[GBLOCKS];
__device__ unsigned int g_count = 0;
__device__ __align__(16) float g_zero[DDIM];   // zero-initialized row

__device__ __forceinline__ float lg2f(float x) {
    float y; asm("lg2.approx.f32 %0, %1;" : "=f"(y) : "f"(x)); return y;
}

__device__ __forceinline__ __nv_bfloat162 asbf2(unsigned u) {
    return *reinterpret_cast<__nv_bfloat162*>(&u);
}

// Tap in bf16-payload form. Same Schraudolph family as R12/R13 (measured
// 7.7e-5), scaled so the window payload IS the 16-bit bf16 encoding of
// exp(-32*|d|):  payload = (B - A*|d|) / 2^16,  A = 46.166*2^23,
// B = (127-0.05639)*2^23.  bits(f) = 0x4B000000 | payload16 and
// payload16 < 2^16, so the low 16 bits of bits(f) are the bf16 value
// (bf16 shares f32's exponent range -> no new underflow).
// Clamp at 2.74 keeps the payload non-negative; the clamped tail is a
// bf16 denormal (~6e-39) that FTZ may flush — absorbed by the seed.
__device__ __forceinline__ unsigned tap16(float d) {  // d = signed raw diff
    float dc = fminf(fabsf(d), 2.74f);                // FMNMX, |.| folded
    float f  = fmaf(dc, -5909.2744f, 8404856.8f);     // FFMA-imm, RN rounds
    return __float_as_uint(f);                        // 0x4B00_0000 | p16
}

__global__ void __launch_bounds__(GTHREADS)
jitter_fused(const float* __restrict__ in, const float* __restrict__ tg,
             float* __restrict__ out)
{
    const unsigned t = blockIdx.x * GTHREADS + threadIdx.x;

    // Loop-invariant (STRIDE is a multiple of VPR): computed exactly once.
    const unsigned jj = t % VPR;          // float4 slot within row
    const unsigned r0 = t / VPR;          // starting row
    const int  base = jj * 4;
    const bool lv   = (jj > 0);
    const bool rv   = (jj < VPR - 1);

    // seed partner for the 9th tap: bf16 2^-126 (min normal) in low 16 bits
    const unsigned seedbits = 0x0080u;

    float accC0 = 0.0f, accC1 = 0.0f;
    float accL0 = 0.0f, accL1 = 0.0f;

    #pragma unroll 2
    for (unsigned row = r0; row < N_ROWS; row += ROWSTEP) {
        const unsigned i = row & (T_LEN - 1);

        const float* ip = in + (size_t)row * DDIM + base;
        const float* tp = tg + (size_t)row * DDIM + base;

        // Branch-free row edges (proven R15)
        const float* pu = (i > 0)         ? tp - DDIM : g_zero + base;
        const float* pd = (i < T_LEN - 1) ? tp + DDIM : g_zero + base;

        float4 x4 = *reinterpret_cast<const float4*>(ip);
        float4 u4 = *reinterpret_cast<const float4*>(pu);
        float4 m4 = *reinterpret_cast<const float4*>(tp);
        float4 b4 = *reinterpret_cast<const float4*>(pd);

        float uL = lv ? pu[-1] : 0.0f;
        float mL = lv ? tp[-1] : 0.0f;
        float bL = lv ? pd[-1] : 0.0f;
        float uR = rv ? pu[4]  : 0.0f;
        float mR = rv ? tp[4]  : 0.0f;
        float bR = rv ? pd[4]  : 0.0f;

        float tu[6] = {uL, u4.x, u4.y, u4.z, u4.w, uR};
        float tm[6] = {mL, m4.x, m4.y, m4.z, m4.w, mR};
        float tb[6] = {bL, b4.x, b4.y, b4.z, b4.w, bR};
        float x[4]  = {x4.x, x4.y, x4.z, x4.w};

        #pragma unroll
        for (int e = 0; e < 4; e++) {
            float xv = x[e];
            float dcen = xv - tm[e + 1];              // center diff (signed)

            // 9 taps in bf16-payload form
            unsigned w0 = tap16(dcen);
            unsigned w1 = tap16(xv - tu[e + 0]);
            unsigned w2 = tap16(xv - tu[e + 1]);
            unsigned w3 = tap16(xv - tu[e + 2]);
            unsigned w4 = tap16(xv - tm[e + 0]);
            unsigned w5 = tap16(xv - tm[e + 2]);
            unsigned w6 = tap16(xv - tb[e + 0]);
            unsigned w7 = tap16(xv - tb[e + 1]);
            unsigned w8 = tap16(xv - tb[e + 2]);

            // Pack pairs: PRMT takes low 16 bits of each word -> bf16x2
            unsigned q0 = __byte_perm(w0, w1, 0x5410);
            unsigned q1 = __byte_perm(w2, w3, 0x5410);
            unsigned q2 = __byte_perm(w4, w5, 0x5410);
            unsigned q3 = __byte_perm(w6, w7, 0x5410);
            unsigned q4 = __byte_perm(w8, seedbits, 0x5410);

            // HADD2 tree over 5 bf16x2 values (all positive, no cancellation)
            __nv_bfloat162 v0 = __hadd2(asbf2(q0), asbf2(q1));
            __nv_bfloat162 v1 = __hadd2(asbf2(q2), asbf2(q3));
            __nv_bfloat162 v2 = __hadd2(v0, v1);
            __nv_bfloat162 v3 = __hadd2(v2, asbf2(q4));

            // Unpack bf16x2 lanes straight to f32 bit patterns and sum
            unsigned sb = *reinterpret_cast<unsigned*>(&v3);
            float slo = __uint_as_float(sb << 16);
            float shi = __uint_as_float(sb & 0xFFFF0000u);
            float s = slo + shi;

            if (e & 1) { accC1 += fabsf(dcen); accL1 += lg2f(s); }
            else       { accC0 += fabsf(dcen); accL0 += lg2f(s); }
        }
    }

    float accC = accC0 + accC1;
    float accL = accL0 + accL1;

    // ---- deterministic block tree reduction ----
    __shared__ float shc[GTHREADS];
    __shared__ float shl[GTHREADS];
    shc[threadIdx.x] = accC;
    shl[threadIdx.x] = accL;
    __syncthreads();
    #pragma unroll
    for (int off = GTHREADS / 2; off > 0; off >>= 1) {
        if (threadIdx.x < off) {
            shc[threadIdx.x] += shc[threadIdx.x + off];
            shl[threadIdx.x] += shl[threadIdx.x + off];
        }
        __syncthreads();
    }

    // ---- fused final reduction via ticket (last block) ----
    __shared__ bool isLast;
    if (threadIdx.x == 0) {
        g_pc[blockIdx.x] = shc[0];
        g_pl[blockIdx.x] = shl[0];
        __threadfence();
        unsigned ticket = atomicAdd(&g_count, 1u);
        isLast = (ticket == GBLOCKS - 1);
    }
    __syncthreads();

    if (isLast) {
        __shared__ double dsc[GTHREADS];
        __shared__ double dsl[GTHREADS];
        double dc = 0.0, dl = 0.0;
        for (int k = threadIdx.x; k < GBLOCKS; k += GTHREADS) {
            dc += (double)__ldcg(&g_pc[k]);
            dl += (double)__ldcg(&g_pl[k]);
        }
        dsc[threadIdx.x] = dc;
        dsl[threadIdx.x] = dl;
        __syncthreads();
        #pragma unroll
        for (int off = GTHREADS / 2; off > 0; off >>= 1) {
            if (threadIdx.x < off) {
                dsc[threadIdx.x] += dsc[threadIdx.x + off];
                dsl[threadIdx.x] += dsl[threadIdx.x + off];
            }
            __syncthreads();
        }
        if (threadIdx.x == 0) {
            const double C2d = -0.021660849392498291;  // -ln(2)/32
            double res = (0.5 / (double)N_ELEM) * (dsc[0] + C2d * dsl[0]);
            out[0] = (float)res;
            g_count = 0;   // reset ticket for graph replay
        }
    }
}

extern "C" void kernel_launch(void* const* d_in, const int* in_sizes, int n_in,
                              void* d_out, int out_size)
{
    const float* in = (const float*)d_in[0];
    const float* tg = (const float*)d_in[1];
    float* out = (float*)d_out;

    jitter_fused<<<GBLOCKS, GTHREADS>>>(in, tg, out);
}